// round 14
// baseline (speedup 1.0000x reference)
#include <cuda_runtime.h>
#include <cuda_fp16.h>
#include <cstdint>

#define NGRAPH 512
#define NPTS   128
#define KNN    24
#define XP     68   // xs pitch: 4-bank skew, conflict-free, no swizzle ALU

// floats: xs[128*68] | fb[128*64] | pw[8192] | sq[128] | pld[64] | nidx bytes
#define SMEM_FLOATS (128 * XP + 8192 + 8192 + 128 + 64)
#define SMEM_BYTES  (SMEM_FLOATS * 4 + NPTS * KNN)

typedef unsigned long long u64;

__device__ __forceinline__ u64 pk2(float lo, float hi) {
    u64 r; asm("mov.b64 %0,{%1,%2};" : "=l"(r) : "f"(lo), "f"(hi)); return r;
}
__device__ __forceinline__ void fma2(u64& d, u64 a, u64 b) {
    asm("fma.rn.f32x2 %0,%1,%2,%0;" : "+l"(d) : "l"(a), "l"(b));
}
__device__ __forceinline__ float hsum2(u64 v) {
    float lo, hi; asm("mov.b64 {%0,%1},%2;" : "=f"(lo), "=f"(hi) : "l"(v));
    return lo + hi;
}

struct Params {
    const float* x_pf;
    const int* batch;
    const float *we1, *be1, *we2, *be2;
    const float *wc1, *bc1, *wc2, *bc2, *wc3, *bc3;
    const float *wo1, *bo1, *wo2, *bo2, *wo3, *bo3, *wo4, *bo4, *wo5, *bo5;
    float* out;
};

__device__ __forceinline__ float elu1(float x) {
    return x > 0.0f ? x : expm1f(x);
}

#define CSWAP(a, b) { unsigned _lo = umin(a, b), _hi = umax(a, b); a = _lo; b = _hi; }

// one top-K extraction round over 8 sorted-head row-chains; interleave into
// fma-dense loops (REDUX latency hides behind the FFMA2 stream)
#define EXTRACT_ROUND(KEY, IBASE, KK)                                       \
    do {                                                                    \
        _Pragma("unroll")                                                   \
        for (int _r = 0; _r < 8; _r++) {                                    \
            unsigned _m = __reduce_min_sync(0xffffffffu, KEY[_r][0]);       \
            if (KEY[_r][0] == _m) {   /* unique lane (keys unique) */       \
                nidx[(IBASE) + _r * KNN + (KK)] = (unsigned char)(_m & 127u);\
                KEY[_r][0] = KEY[_r][1];                                    \
                KEY[_r][1] = KEY[_r][2];                                    \
                KEY[_r][2] = KEY[_r][3];                                    \
                KEY[_r][3] = 0xFFFFFFFFu;                                   \
            }                                                               \
        }                                                                   \
        (KK)++;                                                             \
    } while (0)

__global__ void __launch_bounds__(256, 2) svj_fused(Params p)
{
    extern __shared__ float sm[];
    float* xs  = sm;                     // [128][XP]: features -> a -> h (in-place)
    float* fb  = xs + 128 * XP;          // [128][64]: h1 stage f32 / b values fp16
    __half* fbh = (__half*)fb;           // fp16 view, pitch 64 halves (128B rows)
    float* pwf = fb + 8192;              // 8192 floats: packed weights region
    u64*   pw  = (u64*)pwf;              // pwA [16][64][2] u64, pwB at +2048
    float* sq  = pwf + 8192;             // [128]
    float* pld = sq + 128;               // [64]
    unsigned char* nidx = (unsigned char*)(pld + 64);  // [128][24]

    const int g    = blockIdx.x;
    const int t    = threadIdx.x;
    const int lane = t & 31;
    const int w    = t >> 5;
    const int o    = t & 63;
    const int ngrp = t >> 6;
    const int nb   = ngrp * 32;

    // ---------------- embed ----------------
    if (t < 128)   // stage x_pf in pw region (free until pwe2 staging)
        reinterpret_cast<float4*>(pwf)[t] =
            reinterpret_cast<const float4*>(p.x_pf)[g * NPTS + t];
    __syncthreads();

    {   // h1 = elu(x4 @ we1 + be1) -> fb row-major (f32 phase use of fb)
        float acc[32];
        float b = p.be1[o];
#pragma unroll
        for (int r = 0; r < 32; r++) acc[r] = b;
#pragma unroll
        for (int k = 0; k < 4; k++) {
            float wv = p.we1[k * 64 + o];
#pragma unroll
            for (int r = 0; r < 32; r++)
                acc[r] += pwf[(nb + r) * 4 + k] * wv;
        }
#pragma unroll
        for (int r = 0; r < 32; r++)
            fb[(nb + r) * 64 + o] = elu1(acc[r]);
    }
    __syncthreads();

    {   // stage pwe2[kpp][o][2] (k-pairs of we2)
#pragma unroll
        for (int e = 0; e < 4; e++) {
            int idx = t + 256 * e;
            int kpp = idx >> 6, oo = idx & 63;
            int k0 = 4 * kpp;
            float w0 = p.we2[(k0 + 0) * 64 + oo];
            float w1 = p.we2[(k0 + 1) * 64 + oo];
            float w2 = p.we2[(k0 + 2) * 64 + oo];
            float w3 = p.we2[(k0 + 3) * 64 + oo];
            pw[kpp * 128 + oo * 2 + 0] = pk2(w0, w1);
            pw[kpp * 128 + oo * 2 + 1] = pk2(w2, w3);
        }
    }
    __syncthreads();

    {   // h = elu(h1 @ we2 + be2) -> xs; 2 halves of 16 rows
        float b = p.be2[o];
#pragma unroll
        for (int half = 0; half < 2; half++) {
            u64 acc[16];
#pragma unroll
            for (int r = 0; r < 16; r++) acc[r] = pk2(b, 0.0f);
#pragma unroll 4
            for (int kpp = 0; kpp < 16; kpp++) {
                ulonglong2 wv = *reinterpret_cast<ulonglong2*>(
                    &pw[kpp * 128 + o * 2]);
#pragma unroll
                for (int r = 0; r < 16; r++) {
                    ulonglong2 x2 = *reinterpret_cast<ulonglong2*>(
                        &fb[(nb + half * 16 + r) * 64 + kpp * 4]);
                    fma2(acc[r], x2.x, wv.x);
                    fma2(acc[r], x2.y, wv.y);
                }
            }
#pragma unroll
            for (int r = 0; r < 16; r++) {
                int n = nb + half * 16 + r;
                xs[n * XP + o] = elu1(hsum2(acc[r]));
            }
        }
    }
    __syncthreads();

    const float* WCs[3] = {p.wc1, p.wc2, p.wc3};
    const float* BCs[3] = {p.bc1, p.bc2, p.bc3};

    for (int layer = 0; layer < 3; layer++) {
        // ---- stage packed edge weights + per-node sqnorms, one barrier ----
        {
            const float* wc = WCs[layer];
#pragma unroll
            for (int e = 0; e < 4; e++) {
                int idx = t + 256 * e;
                int kpp = idx >> 6, oo = idx & 63;
                int k0 = 4 * kpp;
                float t0 = wc[(k0 + 0) * 64 + oo], b0 = wc[(64 + k0 + 0) * 64 + oo];
                float t1 = wc[(k0 + 1) * 64 + oo], b1 = wc[(64 + k0 + 1) * 64 + oo];
                float t2 = wc[(k0 + 2) * 64 + oo], b2 = wc[(64 + k0 + 2) * 64 + oo];
                float t3 = wc[(k0 + 3) * 64 + oo], b3 = wc[(64 + k0 + 3) * 64 + oo];
                pw[kpp * 128 + oo * 2 + 0]        = pk2(t0 - b0, t1 - b1);
                pw[kpp * 128 + oo * 2 + 1]        = pk2(t2 - b2, t3 - b3);
                pw[2048 + kpp * 128 + oo * 2 + 0] = pk2(b0, b1);
                pw[2048 + kpp * 128 + oo * 2 + 1] = pk2(b2, b3);
            }
        }
        {
            int row = t >> 1, hh = t & 1;
            const float* xr = xs + row * XP + hh * 32;
            float s = 0.f;
#pragma unroll
            for (int q = 0; q < 8; q++) {
                float4 v = *reinterpret_cast<const float4*>(xr + q * 4);
                s += v.x * v.x + v.y * v.y + v.z * v.z + v.w * v.w;
            }
            s += __shfl_xor_sync(0xffffffffu, s, 1);
            if (!hh) sq[row] = s;
        }
        __syncthreads();

        const int ibase0 = (w * 16) * KNN;
        const int ibase1 = (w * 16 + 8) * KNN;

        // ---- Gram half 0 -> key0 ----
        unsigned key0[8][4];
#pragma unroll
        for (int ib = 0; ib < 2; ib++) {
            const int i0 = w * 16 + ib * 4;
            u64 acc2[4][4];
#pragma unroll
            for (int r = 0; r < 4; r++)
#pragma unroll
                for (int s = 0; s < 4; s++) acc2[r][s] = 0ull;
#pragma unroll 4
            for (int d4 = 0; d4 < 16; d4++) {
                ulonglong2 xj2[4];
#pragma unroll
                for (int s = 0; s < 4; s++)
                    xj2[s] = *reinterpret_cast<const ulonglong2*>(
                        &xs[(s * 32 + lane) * XP + d4 * 4]);
#pragma unroll
                for (int r = 0; r < 4; r++) {
                    ulonglong2 xi2 = *reinterpret_cast<const ulonglong2*>(
                        &xs[(i0 + r) * XP + d4 * 4]);   // broadcast
#pragma unroll
                    for (int s = 0; s < 4; s++) {
                        fma2(acc2[r][s], xi2.x, xj2[s].x);
                        fma2(acc2[r][s], xi2.y, xj2[s].y);
                    }
                }
            }
#pragma unroll
            for (int r = 0; r < 4; r++) {
                float si = sq[i0 + r];
                unsigned* kr = key0[ib * 4 + r];
#pragma unroll
                for (int s = 0; s < 4; s++) {
                    int j = s * 32 + lane;
                    float d = fmaxf(si + sq[j] - 2.f * hsum2(acc2[r][s]), 0.f);
                    // nonneg float: bit order == value order; low 7 bits = idx
                    kr[s] = (__float_as_uint(d) & 0xFFFFFF80u) | (unsigned)j;
                }
                CSWAP(kr[0], kr[1]); CSWAP(kr[2], kr[3]);
                CSWAP(kr[0], kr[2]); CSWAP(kr[1], kr[3]);
                CSWAP(kr[1], kr[2]);
            }
        }

        // ---- Gram half 1 -> key1, with key0 extraction interleaved ----
        // (key0 dies here; only one key set + one acc set live at any time)
        unsigned key1[8][4];
        {
            int kk0 = 0;
#pragma unroll
            for (int ib = 0; ib < 2; ib++) {
                const int i0 = w * 16 + 8 + ib * 4;
                u64 acc2[4][4];
#pragma unroll
                for (int r = 0; r < 4; r++)
#pragma unroll
                    for (int s = 0; s < 4; s++) acc2[r][s] = 0ull;
#pragma unroll
                for (int d4 = 0; d4 < 16; d4++) {
                    ulonglong2 xj2[4];
#pragma unroll
                    for (int s = 0; s < 4; s++)
                        xj2[s] = *reinterpret_cast<const ulonglong2*>(
                            &xs[(s * 32 + lane) * XP + d4 * 4]);
#pragma unroll
                    for (int r = 0; r < 4; r++) {
                        ulonglong2 xi2 = *reinterpret_cast<const ulonglong2*>(
                            &xs[(i0 + r) * XP + d4 * 4]);   // broadcast
#pragma unroll
                        for (int s = 0; s < 4; s++) {
                            fma2(acc2[r][s], xi2.x, xj2[s].x);
                            fma2(acc2[r][s], xi2.y, xj2[s].y);
                        }
                    }
                    if (ib * 16 + d4 < KNN)   // 24 rounds; folds under unroll
                        EXTRACT_ROUND(key0, ibase0, kk0);
                }
#pragma unroll
                for (int r = 0; r < 4; r++) {
                    float si = sq[i0 + r];
                    unsigned* kr = key1[ib * 4 + r];
#pragma unroll
                    for (int s = 0; s < 4; s++) {
                        int j = s * 32 + lane;
                        float d = fmaxf(si + sq[j] - 2.f * hsum2(acc2[r][s]), 0.f);
                        kr[s] = (__float_as_uint(d) & 0xFFFFFF80u) | (unsigned)j;
                    }
                    CSWAP(kr[0], kr[1]); CSWAP(kr[2], kr[3]);
                    CSWAP(kr[0], kr[2]); CSWAP(kr[1], kr[3]);
                    CSWAP(kr[1], kr[2]);
                }
            }
        }
        __syncthreads();

        // ---- a/b GEMM in 4x8-row quarters; key1 extraction interleaved ----
        // liveness: key1 (32) + aa/bb (32) + transients -> no spill
        {
            const float bcv = BCs[layer][o];
            int kk1 = 0;
#pragma unroll
            for (int q = 0; q < 4; q++) {
                const int rb = nb + q * 8;
                u64 aa[8], bb[8];
#pragma unroll
                for (int r = 0; r < 8; r++) {
                    aa[r] = pk2(bcv, 0.0f);
                    bb[r] = 0ull;
                }
#pragma unroll
                for (int kpp = 0; kpp < 16; kpp++) {
                    ulonglong2 wA = *reinterpret_cast<ulonglong2*>(
                        &pw[kpp * 128 + o * 2]);
                    ulonglong2 wB = *reinterpret_cast<ulonglong2*>(
                        &pw[2048 + kpp * 128 + o * 2]);
#pragma unroll
                    for (int r = 0; r < 8; r++) {
                        ulonglong2 x2 = *reinterpret_cast<const ulonglong2*>(
                            &xs[(rb + r) * XP + kpp * 4]);   // broadcast
                        fma2(aa[r], x2.x, wA.x);
                        fma2(aa[r], x2.y, wA.y);
                        fma2(bb[r], x2.x, wB.x);
                        fma2(bb[r], x2.y, wB.y);
                    }
                    if (q * 16 + kpp < KNN)   // 24 rounds; folds under unroll
                        EXTRACT_ROUND(key1, ibase1, kk1);
                }
                // group's reads of this quarter's xs rows are complete
                asm volatile("bar.sync %0, 64;" :: "r"(1 + ngrp) : "memory");
#pragma unroll
                for (int r = 0; r < 8; r++) {
                    int n = rb + r;
                    xs[n * XP + o] = hsum2(aa[r]);                 // a over x
                    fbh[n * 64 + o] = __float2half(hsum2(bb[r]));  // b fp16
                }
            }
        }
        __syncthreads();

        // ---- gather-max (fp16 b): h_i = elu(a_i + max_j b_j) -> xs ----
        {
            const int hw = lane >> 4;
            const int ln = lane & 15;
            for (int pr = w; pr < 64; pr += 8) {
                const int i = pr * 2 + hw;
                float4 av = *reinterpret_cast<float4*>(&xs[i * XP + ln * 4]);
                unsigned iw[6];
                const unsigned* ip32 =
                    reinterpret_cast<const unsigned*>(&nidx[i * KNN]);
#pragma unroll
                for (int q = 0; q < 6; q++) iw[q] = ip32[q];
                __half2 mA[4], mB[4];
#pragma unroll
                for (int c = 0; c < 4; c++) {
                    mA[c] = __float2half2_rn(-60000.f);
                    mB[c] = __float2half2_rn(-60000.f);
                }
#pragma unroll
                for (int k = 0; k < KNN; k++) {
                    int j = (iw[k >> 2] >> ((k & 3) * 8)) & 0xFF;
                    uint2 v = *reinterpret_cast<const uint2*>(
                        &fbh[j * 64 + ln * 4]);
                    __half2 b01 = *reinterpret_cast<__half2*>(&v.x);
                    __half2 b23 = *reinterpret_cast<__half2*>(&v.y);
                    int ch = k & 3;          // 4 independent chains
                    mA[ch] = __hmax2(mA[ch], b01);
                    mB[ch] = __hmax2(mB[ch], b23);
                }
                __half2 fA = __hmax2(__hmax2(mA[0], mA[1]), __hmax2(mA[2], mA[3]));
                __half2 fB = __hmax2(__hmax2(mB[0], mB[1]), __hmax2(mB[2], mB[3]));
                float2 f01 = __half22float2(fA);
                float2 f23 = __half22float2(fB);
                float4 hv;
                hv.x = elu1(av.x + f01.x);
                hv.y = elu1(av.y + f01.y);
                hv.z = elu1(av.z + f23.x);
                hv.w = elu1(av.w + f23.y);
                *reinterpret_cast<float4*>(&xs[i * XP + ln * 4]) = hv;
            }
        }
        __syncthreads();
    }

    // ---------------- sum pool ----------------
    {
        float s = 0.f;
        for (int r = 0; r < 32; r++) {
            int i = nb + r;
            s += xs[i * XP + o];
        }
        fb[ngrp * 64 + o] = s;
    }
    __syncthreads();
    if (t < 64) pld[t] = fb[t] + fb[64 + t] + fb[128 + t] + fb[192 + t];
    __syncthreads();

    // ---------------- head MLP ----------------
    if (t < 64) {
        float v = p.bo1[t];
        for (int k = 0; k < 64; k++) v += pld[k] * p.wo1[k * 64 + t];
        sq[t] = elu1(v);
    }
    __syncthreads();
    if (t < 32) {
        float v = p.bo2[t];
        for (int k = 0; k < 64; k++) v += sq[k] * p.wo2[k * 32 + t];
        sq[64 + t] = elu1(v);
    }
    __syncthreads();
    if (t < 32) {
        float v = p.bo3[t];
        for (int k = 0; k < 32; k++) v += sq[64 + k] * p.wo3[k * 32 + t];
        pld[t] = elu1(v);
    }
    __syncthreads();
    if (t < 8) {
        float v = p.bo4[t];
        for (int k = 0; k < 32; k++) v += pld[k] * p.wo4[k * 8 + t];
        sq[t] = elu1(v);
    }
    __syncthreads();
    if (t == 0) {
        float v = p.bo5[0];
        for (int k = 0; k < 8; k++) v += sq[k] * p.wo5[k];
        p.out[g] = v;
    }
}

__global__ void write_batch_f32(const int* __restrict__ b,
                                float* __restrict__ out, int n) {
    int i = blockIdx.x * blockDim.x + threadIdx.x;
    if (i < n) out[NGRAPH + i] = (float)b[i];
}

extern "C" void kernel_launch(void* const* d_in, const int* in_sizes, int n_in,
                              void* d_out, int out_size)
{
    Params p;
    p.x_pf  = (const float*)d_in[0];
    p.batch = (const int*)d_in[1];
    p.we1 = (const float*)d_in[2];  p.be1 = (const float*)d_in[3];
    p.we2 = (const float*)d_in[4];  p.be2 = (const float*)d_in[5];
    p.wc1 = (const float*)d_in[6];  p.bc1 = (const float*)d_in[7];
    p.wc2 = (const float*)d_in[8];  p.bc2 = (const float*)d_in[9];
    p.wc3 = (const float*)d_in[10]; p.bc3 = (const float*)d_in[11];
    p.wo1 = (const float*)d_in[12]; p.bo1 = (const float*)d_in[13];
    p.wo2 = (const float*)d_in[14]; p.bo2 = (const float*)d_in[15];
    p.wo3 = (const float*)d_in[16]; p.bo3 = (const float*)d_in[17];
    p.wo4 = (const float*)d_in[18]; p.bo4 = (const float*)d_in[19];
    p.wo5 = (const float*)d_in[20]; p.bo5 = (const float*)d_in[21];
    p.out = (float*)d_out;

    // batch passthrough FIRST so ncu (-s 5 -c 1) lands on svj_fused.
    {
        int n = in_sizes[1];
        int room = out_size - NGRAPH;
        if (n > room) n = room;
        if (n > 0)
            write_batch_f32<<<(n + 255) / 256, 256>>>(p.batch, (float*)d_out, n);
    }

    cudaFuncSetAttribute(svj_fused,
        cudaFuncAttributeMaxDynamicSharedMemorySize, SMEM_BYTES);
    svj_fused<<<NGRAPH, 256, SMEM_BYTES>>>(p);
}

// round 15
// speedup vs baseline: 1.4416x; 1.4416x over previous
#include <cuda_runtime.h>
#include <cuda_fp16.h>
#include <cstdint>

#define NGRAPH 512
#define NPTS   128
#define KNN    24
#define XP     68   // xs pitch: 4-bank skew, conflict-free, no swizzle ALU

// floats: xs[128*68] | fb[128*64] | pw[8192] | sq[128] | pld[64] | nidx bytes
#define SMEM_FLOATS (128 * XP + 8192 + 8192 + 128 + 64)
#define SMEM_BYTES  (SMEM_FLOATS * 4 + NPTS * KNN)

typedef unsigned long long u64;

__device__ __forceinline__ u64 pk2(float lo, float hi) {
    u64 r; asm("mov.b64 %0,{%1,%2};" : "=l"(r) : "f"(lo), "f"(hi)); return r;
}
__device__ __forceinline__ void fma2(u64& d, u64 a, u64 b) {
    asm("fma.rn.f32x2 %0,%1,%2,%0;" : "+l"(d) : "l"(a), "l"(b));
}
__device__ __forceinline__ float hsum2(u64 v) {
    float lo, hi; asm("mov.b64 {%0,%1},%2;" : "=f"(lo), "=f"(hi) : "l"(v));
    return lo + hi;
}

struct Params {
    const float* x_pf;
    const int* batch;
    const float *we1, *be1, *we2, *be2;
    const float *wc1, *bc1, *wc2, *bc2, *wc3, *bc3;
    const float *wo1, *bo1, *wo2, *bo2, *wo3, *bo3, *wo4, *bo4, *wo5, *bo5;
    float* out;
};

__device__ __forceinline__ float elu1(float x) {
    return x > 0.0f ? x : expm1f(x);
}

#define CSWAP(a, b) { unsigned _lo = umin(a, b), _hi = umax(a, b); a = _lo; b = _hi; }

__global__ void __launch_bounds__(256, 2) svj_fused(Params p)
{
    extern __shared__ float sm[];
    float* xs  = sm;                     // [128][XP]: features -> a -> h (in-place)
    float* fb  = xs + 128 * XP;          // [128][64]: h1 stage f32 / b values fp16
    __half* fbh = (__half*)fb;           // fp16 view, pitch 64 halves (128B rows)
    float* pwf = fb + 8192;              // 8192 floats: packed weights region
    u64*   pw  = (u64*)pwf;              // pwA [16][64][2] u64, pwB at +2048
    float* sq  = pwf + 8192;             // [128]
    float* pld = sq + 128;               // [64]
    unsigned char* nidx = (unsigned char*)(pld + 64);  // [128][24]

    const int g    = blockIdx.x;
    const int t    = threadIdx.x;
    const int lane = t & 31;
    const int w    = t >> 5;
    const int o    = t & 63;
    const int ngrp = t >> 6;
    const int nb   = ngrp * 32;

    // ---------------- embed ----------------
    if (t < 128)   // stage x_pf in pw region (free until pwe2 staging)
        reinterpret_cast<float4*>(pwf)[t] =
            reinterpret_cast<const float4*>(p.x_pf)[g * NPTS + t];
    __syncthreads();

    {   // h1 = elu(x4 @ we1 + be1) -> fb row-major (f32 phase use of fb)
        float acc[32];
        float b = p.be1[o];
#pragma unroll
        for (int r = 0; r < 32; r++) acc[r] = b;
#pragma unroll
        for (int k = 0; k < 4; k++) {
            float wv = p.we1[k * 64 + o];
#pragma unroll
            for (int r = 0; r < 32; r++)
                acc[r] += pwf[(nb + r) * 4 + k] * wv;
        }
#pragma unroll
        for (int r = 0; r < 32; r++)
            fb[(nb + r) * 64 + o] = elu1(acc[r]);
    }
    __syncthreads();

    {   // stage pwe2[kpp][o][2] (k-pairs of we2)
#pragma unroll
        for (int e = 0; e < 4; e++) {
            int idx = t + 256 * e;
            int kpp = idx >> 6, oo = idx & 63;
            int k0 = 4 * kpp;
            float w0 = p.we2[(k0 + 0) * 64 + oo];
            float w1 = p.we2[(k0 + 1) * 64 + oo];
            float w2 = p.we2[(k0 + 2) * 64 + oo];
            float w3 = p.we2[(k0 + 3) * 64 + oo];
            pw[kpp * 128 + oo * 2 + 0] = pk2(w0, w1);
            pw[kpp * 128 + oo * 2 + 1] = pk2(w2, w3);
        }
    }
    __syncthreads();

    {   // h = elu(h1 @ we2 + be2) -> xs; 2 halves of 16 rows
        float b = p.be2[o];
#pragma unroll
        for (int half = 0; half < 2; half++) {
            u64 acc[16];
#pragma unroll
            for (int r = 0; r < 16; r++) acc[r] = pk2(b, 0.0f);
#pragma unroll 4
            for (int kpp = 0; kpp < 16; kpp++) {
                ulonglong2 wv = *reinterpret_cast<ulonglong2*>(
                    &pw[kpp * 128 + o * 2]);
#pragma unroll
                for (int r = 0; r < 16; r++) {
                    ulonglong2 x2 = *reinterpret_cast<ulonglong2*>(
                        &fb[(nb + half * 16 + r) * 64 + kpp * 4]);
                    fma2(acc[r], x2.x, wv.x);
                    fma2(acc[r], x2.y, wv.y);
                }
            }
#pragma unroll
            for (int r = 0; r < 16; r++) {
                int n = nb + half * 16 + r;
                xs[n * XP + o] = elu1(hsum2(acc[r]));
            }
        }
    }
    __syncthreads();

    const float* WCs[3] = {p.wc1, p.wc2, p.wc3};
    const float* BCs[3] = {p.bc1, p.bc2, p.bc3};

    for (int layer = 0; layer < 3; layer++) {
        // ---- stage packed edge weights + per-node sqnorms, one barrier ----
        {
            const float* wc = WCs[layer];
#pragma unroll
            for (int e = 0; e < 4; e++) {
                int idx = t + 256 * e;
                int kpp = idx >> 6, oo = idx & 63;
                int k0 = 4 * kpp;
                float t0 = wc[(k0 + 0) * 64 + oo], b0 = wc[(64 + k0 + 0) * 64 + oo];
                float t1 = wc[(k0 + 1) * 64 + oo], b1 = wc[(64 + k0 + 1) * 64 + oo];
                float t2 = wc[(k0 + 2) * 64 + oo], b2 = wc[(64 + k0 + 2) * 64 + oo];
                float t3 = wc[(k0 + 3) * 64 + oo], b3 = wc[(64 + k0 + 3) * 64 + oo];
                pw[kpp * 128 + oo * 2 + 0]        = pk2(t0 - b0, t1 - b1);
                pw[kpp * 128 + oo * 2 + 1]        = pk2(t2 - b2, t3 - b3);
                pw[2048 + kpp * 128 + oo * 2 + 0] = pk2(b0, b1);
                pw[2048 + kpp * 128 + oo * 2 + 1] = pk2(b2, b3);
            }
        }
        {
            int row = t >> 1, hh = t & 1;
            const float* xr = xs + row * XP + hh * 32;
            float s = 0.f;
#pragma unroll
            for (int q = 0; q < 8; q++) {
                float4 v = *reinterpret_cast<const float4*>(xr + q * 4);
                s += v.x * v.x + v.y * v.y + v.z * v.z + v.w * v.w;
            }
            s += __shfl_xor_sync(0xffffffffu, s, 1);
            if (!hh) sq[row] = s;
        }
        __syncthreads();

        // ---- distances + top-K per 8-row half; 8x4 Gram blocks (xj /2) ----
        for (int half = 0; half < 2; half++) {
            const int i0 = w * 16 + half * 8;
            unsigned key[8][4];
            {
                u64 acc2[8][4];
#pragma unroll
                for (int r = 0; r < 8; r++)
#pragma unroll
                    for (int s = 0; s < 4; s++) acc2[r][s] = 0ull;

#pragma unroll 2
                for (int d4 = 0; d4 < 16; d4++) {
                    ulonglong2 xj2[4];
#pragma unroll
                    for (int s = 0; s < 4; s++)
                        xj2[s] = *reinterpret_cast<const ulonglong2*>(
                            &xs[(s * 32 + lane) * XP + d4 * 4]);
#pragma unroll
                    for (int r = 0; r < 8; r++) {
                        ulonglong2 xi2 = *reinterpret_cast<const ulonglong2*>(
                            &xs[(i0 + r) * XP + d4 * 4]);   // broadcast
#pragma unroll
                        for (int s = 0; s < 4; s++) {
                            fma2(acc2[r][s], xi2.x, xj2[s].x);
                            fma2(acc2[r][s], xi2.y, xj2[s].y);
                        }
                    }
                }
#pragma unroll
                for (int r = 0; r < 8; r++) {
                    float si = sq[i0 + r];
                    unsigned* kr = key[r];
#pragma unroll
                    for (int s = 0; s < 4; s++) {
                        int j = s * 32 + lane;
                        float d = fmaxf(si + sq[j] - 2.f * hsum2(acc2[r][s]), 0.f);
                        // nonneg float: bit order == value order; low 7 bits = idx
                        kr[s] = (__float_as_uint(d) & 0xFFFFFF80u) | (unsigned)j;
                    }
                    CSWAP(kr[0], kr[1]); CSWAP(kr[2], kr[3]);
                    CSWAP(kr[0], kr[2]); CSWAP(kr[1], kr[3]);
                    CSWAP(kr[1], kr[2]);
                }
            }
            const int ibase = i0 * KNN;
            for (int k = 0; k < KNN; k++) {
#pragma unroll
                for (int r = 0; r < 8; r++) {
                    unsigned m = __reduce_min_sync(0xffffffffu, key[r][0]);
                    if (key[r][0] == m) {   // exactly one lane (keys unique)
                        nidx[ibase + r * KNN + k] = (unsigned char)(m & 127u);
                        key[r][0] = key[r][1];
                        key[r][1] = key[r][2];
                        key[r][2] = key[r][3];
                        key[r][3] = 0xFFFFFFFFu;
                    }
                }
            }
        }
        __syncthreads();

        // ---- a = x@(Wt-Wb)+bc -> xs (in-place) ; b = x@Wb -> fbh fp16 ----
        {
            const float bcv = BCs[layer][o];
#pragma unroll
            for (int half = 0; half < 2; half++) {
                u64 aa[16], bb[16];
#pragma unroll
                for (int r = 0; r < 16; r++) {
                    aa[r] = pk2(bcv, 0.0f);
                    bb[r] = 0ull;
                }
#pragma unroll 4
                for (int kpp = 0; kpp < 16; kpp++) {
                    ulonglong2 wA = *reinterpret_cast<ulonglong2*>(
                        &pw[kpp * 128 + o * 2]);
                    ulonglong2 wB = *reinterpret_cast<ulonglong2*>(
                        &pw[2048 + kpp * 128 + o * 2]);
#pragma unroll
                    for (int r = 0; r < 16; r++) {
                        int n = nb + half * 16 + r;
                        ulonglong2 x2 = *reinterpret_cast<const ulonglong2*>(
                            &xs[n * XP + kpp * 4]);   // broadcast
                        fma2(aa[r], x2.x, wA.x);
                        fma2(aa[r], x2.y, wA.y);
                        fma2(bb[r], x2.x, wB.x);
                        fma2(bb[r], x2.y, wB.y);
                    }
                }
                // group's reads of these 16 xs rows are complete
                asm volatile("bar.sync %0, 64;" :: "r"(1 + ngrp) : "memory");
#pragma unroll
                for (int r = 0; r < 16; r++) {
                    int n = nb + half * 16 + r;
                    xs[n * XP + o] = hsum2(aa[r]);                 // a over x
                    fbh[n * 64 + o] = __float2half(hsum2(bb[r]));  // b fp16
                }
            }
        }
        __syncthreads();

        // ---- gather-max (fp16 b): h_i = elu(a_i + max_j b_j) -> xs ----
        {
            const int hw = lane >> 4;
            const int ln = lane & 15;
            for (int pr = w; pr < 64; pr += 8) {
                const int i = pr * 2 + hw;
                float4 av = *reinterpret_cast<float4*>(&xs[i * XP + ln * 4]);
                unsigned iw[6];
                const unsigned* ip32 =
                    reinterpret_cast<const unsigned*>(&nidx[i * KNN]);
#pragma unroll
                for (int q = 0; q < 6; q++) iw[q] = ip32[q];
                __half2 mA[4], mB[4];
#pragma unroll
                for (int c = 0; c < 4; c++) {
                    mA[c] = __float2half2_rn(-60000.f);
                    mB[c] = __float2half2_rn(-60000.f);
                }
#pragma unroll
                for (int k = 0; k < KNN; k++) {
                    int j = (iw[k >> 2] >> ((k & 3) * 8)) & 0xFF;
                    uint2 v = *reinterpret_cast<const uint2*>(
                        &fbh[j * 64 + ln * 4]);
                    __half2 b01 = *reinterpret_cast<__half2*>(&v.x);
                    __half2 b23 = *reinterpret_cast<__half2*>(&v.y);
                    int ch = k & 3;          // 4 independent chains
                    mA[ch] = __hmax2(mA[ch], b01);
                    mB[ch] = __hmax2(mB[ch], b23);
                }
                __half2 fA = __hmax2(__hmax2(mA[0], mA[1]), __hmax2(mA[2], mA[3]));
                __half2 fB = __hmax2(__hmax2(mB[0], mB[1]), __hmax2(mB[2], mB[3]));
                float2 f01 = __half22float2(fA);
                float2 f23 = __half22float2(fB);
                float4 hv;
                hv.x = elu1(av.x + f01.x);
                hv.y = elu1(av.y + f01.y);
                hv.z = elu1(av.z + f23.x);
                hv.w = elu1(av.w + f23.y);
                *reinterpret_cast<float4*>(&xs[i * XP + ln * 4]) = hv;
            }
        }
        __syncthreads();
    }

    // ---------------- sum pool ----------------
    {
        float s = 0.f;
        for (int r = 0; r < 32; r++) {
            int i = nb + r;
            s += xs[i * XP + o];
        }
        fb[ngrp * 64 + o] = s;
    }
    __syncthreads();
    if (t < 64) pld[t] = fb[t] + fb[64 + t] + fb[128 + t] + fb[192 + t];
    __syncthreads();

    // ---------------- head MLP ----------------
    if (t < 64) {
        float v = p.bo1[t];
        for (int k = 0; k < 64; k++) v += pld[k] * p.wo1[k * 64 + t];
        sq[t] = elu1(v);
    }
    __syncthreads();
    if (t < 32) {
        float v = p.bo2[t];
        for (int k = 0; k < 64; k++) v += sq[k] * p.wo2[k * 32 + t];
        sq[64 + t] = elu1(v);
    }
    __syncthreads();
    if (t < 32) {
        float v = p.bo3[t];
        for (int k = 0; k < 32; k++) v += sq[64 + k] * p.wo3[k * 32 + t];
        pld[t] = elu1(v);
    }
    __syncthreads();
    if (t < 8) {
        float v = p.bo4[t];
        for (int k = 0; k < 32; k++) v += pld[k] * p.wo4[k * 8 + t];
        sq[t] = elu1(v);
    }
    __syncthreads();
    if (t == 0) {
        float v = p.bo5[0];
        for (int k = 0; k < 8; k++) v += sq[k] * p.wo5[k];
        p.out[g] = v;
    }
}

__global__ void write_batch_f32(const int* __restrict__ b,
                                float* __restrict__ out, int n) {
    int i = blockIdx.x * blockDim.x + threadIdx.x;
    if (i < n) out[NGRAPH + i] = (float)b[i];
}

extern "C" void kernel_launch(void* const* d_in, const int* in_sizes, int n_in,
                              void* d_out, int out_size)
{
    Params p;
    p.x_pf  = (const float*)d_in[0];
    p.batch = (const int*)d_in[1];
    p.we1 = (const float*)d_in[2];  p.be1 = (const float*)d_in[3];
    p.we2 = (const float*)d_in[4];  p.be2 = (const float*)d_in[5];
    p.wc1 = (const float*)d_in[6];  p.bc1 = (const float*)d_in[7];
    p.wc2 = (const float*)d_in[8];  p.bc2 = (const float*)d_in[9];
    p.wc3 = (const float*)d_in[10]; p.bc3 = (const float*)d_in[11];
    p.wo1 = (const float*)d_in[12]; p.bo1 = (const float*)d_in[13];
    p.wo2 = (const float*)d_in[14]; p.bo2 = (const float*)d_in[15];
    p.wo3 = (const float*)d_in[16]; p.bo3 = (const float*)d_in[17];
    p.wo4 = (const float*)d_in[18]; p.bo4 = (const float*)d_in[19];
    p.wo5 = (const float*)d_in[20]; p.bo5 = (const float*)d_in[21];
    p.out = (float*)d_out;

    // batch passthrough FIRST so ncu (-s 5 -c 1) lands on svj_fused.
    {
        int n = in_sizes[1];
        int room = out_size - NGRAPH;
        if (n > room) n = room;
        if (n > 0)
            write_batch_f32<<<(n + 255) / 256, 256>>>(p.batch, (float*)d_out, n);
    }

    cudaFuncSetAttribute(svj_fused,
        cudaFuncAttributeMaxDynamicSharedMemorySize, SMEM_BYTES);
    svj_fused<<<NGRAPH, 256, SMEM_BYTES>>>(p);
}